// round 1
// baseline (speedup 1.0000x reference)
#include <cuda_runtime.h>
#include <math.h>

#define BB 32
#define NN 500
#define MM 500
#define DD 256

// Scratch (allocation-free: __device__ globals)
static __device__ float g_KE2[(size_t)BB * MM * 2 * DD];  // [b][m][2d]: even=exp(k)*v, odd=exp(k)
static __device__ float g_SQ [(size_t)BB * NN * DD];      // sigmoid(q0@Wq0^T + q1@Wq1^T)
static __device__ float g_EB [(size_t)BB * NN * MM];      // exp(-a1*ls*cost + mask)
static __device__ float g_AAFM[(size_t)BB * NN * DD];     // sigmoid(q) * num/den
static __device__ float g_S  [(size_t)BB * NN * MM];      // pre-softmax logits

// ---------------------------------------------------------------------------
// proj_kv: k = jobs@Wk^T, v = jobs@Wv^T; store interleaved [exp(k)*v, exp(k)]
// block: 64 rows(m) x 64 cols(e); 256 threads, 4x4 micro-tile, dual accumulator
// ---------------------------------------------------------------------------
__global__ __launch_bounds__(256) void proj_kv_kernel(
    const float* __restrict__ jobs, const float* __restrict__ Wk,
    const float* __restrict__ Wv)
{
    __shared__ float sA[16][68];
    __shared__ float sK[16][68];
    __shared__ float sV[16][68];
    const int b  = blockIdx.z;
    const int m0 = blockIdx.y * 64;
    const int e0 = blockIdx.x * 64;
    const int tid = threadIdx.x;
    const int tx = tid & 15, ty = tid >> 4;
    const int lr = tid >> 2, lc = (tid & 3) << 2;
    const float* A = jobs + (size_t)b * MM * DD;
    float ak[4][4] = {}, av[4][4] = {};

    for (int k0 = 0; k0 < DD; k0 += 16) {
        float4 a = make_float4(0.f, 0.f, 0.f, 0.f);
        if (m0 + lr < MM) a = *(const float4*)(A + (size_t)(m0 + lr) * DD + k0 + lc);
        sA[lc + 0][lr] = a.x; sA[lc + 1][lr] = a.y;
        sA[lc + 2][lr] = a.z; sA[lc + 3][lr] = a.w;
        float4 wk = *(const float4*)(Wk + (size_t)(e0 + lr) * DD + k0 + lc);
        sK[lc + 0][lr] = wk.x; sK[lc + 1][lr] = wk.y;
        sK[lc + 2][lr] = wk.z; sK[lc + 3][lr] = wk.w;
        float4 wv = *(const float4*)(Wv + (size_t)(e0 + lr) * DD + k0 + lc);
        sV[lc + 0][lr] = wv.x; sV[lc + 1][lr] = wv.y;
        sV[lc + 2][lr] = wv.z; sV[lc + 3][lr] = wv.w;
        __syncthreads();
#pragma unroll
        for (int k = 0; k < 16; ++k) {
            float4 af = *(const float4*)&sA[k][ty << 2];
            float4 bk = *(const float4*)&sK[k][tx << 2];
            float4 bv = *(const float4*)&sV[k][tx << 2];
            float ar[4] = {af.x, af.y, af.z, af.w};
            float kr[4] = {bk.x, bk.y, bk.z, bk.w};
            float vr[4] = {bv.x, bv.y, bv.z, bv.w};
#pragma unroll
            for (int r = 0; r < 4; ++r)
#pragma unroll
                for (int c = 0; c < 4; ++c) {
                    ak[r][c] = fmaf(ar[r], kr[c], ak[r][c]);
                    av[r][c] = fmaf(ar[r], vr[c], av[r][c]);
                }
        }
        __syncthreads();
    }
#pragma unroll
    for (int r = 0; r < 4; ++r) {
        int m = m0 + (ty << 2) + r;
        if (m >= MM) continue;
        float* out = g_KE2 + ((size_t)b * MM + m) * (2 * DD);
#pragma unroll
        for (int c = 0; c < 4; ++c) {
            int e = e0 + (tx << 2) + c;
            float ek = expf(ak[r][c]);
            float2 pr = make_float2(ek * av[r][c], ek);
            *(float2*)(out + 2 * e) = pr;
        }
    }
}

// ---------------------------------------------------------------------------
// proj_q: q = q0@Wq0^T + q1@Wq1^T; store sigmoid(q)
// ---------------------------------------------------------------------------
__global__ __launch_bounds__(256) void proj_q_kernel(
    const float* __restrict__ q0, const float* __restrict__ Wq0,
    const float* __restrict__ q1, const float* __restrict__ Wq1)
{
    __shared__ float sA[16][68];
    __shared__ float sW[16][68];
    const int b  = blockIdx.z;
    const int n0 = blockIdx.y * 64;
    const int e0 = blockIdx.x * 64;
    const int tid = threadIdx.x;
    const int tx = tid & 15, ty = tid >> 4;
    const int lr = tid >> 2, lc = (tid & 3) << 2;
    float acc[4][4] = {};

    for (int p = 0; p < 2; ++p) {
        const float* A = (p ? q1 : q0) + (size_t)b * NN * DD;
        const float* W = p ? Wq1 : Wq0;
        for (int k0 = 0; k0 < DD; k0 += 16) {
            float4 a = make_float4(0.f, 0.f, 0.f, 0.f);
            if (n0 + lr < NN) a = *(const float4*)(A + (size_t)(n0 + lr) * DD + k0 + lc);
            sA[lc + 0][lr] = a.x; sA[lc + 1][lr] = a.y;
            sA[lc + 2][lr] = a.z; sA[lc + 3][lr] = a.w;
            float4 w = *(const float4*)(W + (size_t)(e0 + lr) * DD + k0 + lc);
            sW[lc + 0][lr] = w.x; sW[lc + 1][lr] = w.y;
            sW[lc + 2][lr] = w.z; sW[lc + 3][lr] = w.w;
            __syncthreads();
#pragma unroll
            for (int k = 0; k < 16; ++k) {
                float4 af = *(const float4*)&sA[k][ty << 2];
                float4 bf = *(const float4*)&sW[k][tx << 2];
                float ar[4] = {af.x, af.y, af.z, af.w};
                float br[4] = {bf.x, bf.y, bf.z, bf.w};
#pragma unroll
                for (int r = 0; r < 4; ++r)
#pragma unroll
                    for (int c = 0; c < 4; ++c)
                        acc[r][c] = fmaf(ar[r], br[c], acc[r][c]);
            }
            __syncthreads();
        }
    }
#pragma unroll
    for (int r = 0; r < 4; ++r) {
        int n = n0 + (ty << 2) + r;
        if (n >= NN) continue;
        float* out = g_SQ + ((size_t)b * NN + n) * DD + e0 + (tx << 2);
        float4 o;
        o.x = 1.f / (1.f + expf(-acc[r][0]));
        o.y = 1.f / (1.f + expf(-acc[r][1]));
        o.z = 1.f / (1.f + expf(-acc[r][2]));
        o.w = 1.f / (1.f + expf(-acc[r][3]));
        *(float4*)out = o;
    }
}

// ---------------------------------------------------------------------------
// eb: exp_bias = exp(-a1*ls*cost + mask)
// ---------------------------------------------------------------------------
__global__ void eb_kernel(const float* __restrict__ cost,
                          const float* __restrict__ mask,
                          const float* __restrict__ alpha1,
                          const float* __restrict__ log_scale)
{
    const float s1 = -alpha1[0] * log_scale[0];
    const size_t total4 = (size_t)BB * NN * MM / 4;
    const float4* c4 = (const float4*)cost;
    const float4* m4 = (const float4*)mask;
    float4* e4 = (float4*)g_EB;
    for (size_t i = (size_t)blockIdx.x * blockDim.x + threadIdx.x; i < total4;
         i += (size_t)gridDim.x * blockDim.x) {
        float4 c = c4[i], mk = m4[i];
        float4 r;
        r.x = expf(fmaf(s1, c.x, mk.x));
        r.y = expf(fmaf(s1, c.y, mk.y));
        r.z = expf(fmaf(s1, c.z, mk.z));
        r.w = expf(fmaf(s1, c.w, mk.w));
        e4[i] = r;
    }
}

// ---------------------------------------------------------------------------
// aafm: [num|den](n, 2d) = EB(n,m) @ KE2(m, 2d); aafm = SQ * num/den
// block: 64 n x 128 j (interleaved cols), k-tile 16 over m; 4x8 micro
// ---------------------------------------------------------------------------
__global__ __launch_bounds__(256) void aafm_kernel()
{
    __shared__ float sA[16][68];    // [m][n]
    __shared__ float sB[16][132];   // [m][j]
    const int b  = blockIdx.z;
    const int n0 = blockIdx.y * 64;
    const int j0 = blockIdx.x * 128;
    const int tid = threadIdx.x;
    const int tx = tid & 15, ty = tid >> 4;
    const int lrA = tid >> 2, lcA = (tid & 3) << 2;
    const float* EBb = g_EB  + (size_t)b * NN * MM;
    const float* Bb  = g_KE2 + (size_t)b * MM * 2 * DD;
    float acc[4][8] = {};

    for (int k0 = 0; k0 < MM; k0 += 16) {
        float4 a = make_float4(0.f, 0.f, 0.f, 0.f);
        if (n0 + lrA < NN && k0 + lcA < MM)
            a = *(const float4*)(EBb + (size_t)(n0 + lrA) * MM + k0 + lcA);
        sA[lcA + 0][lrA] = a.x; sA[lcA + 1][lrA] = a.y;
        sA[lcA + 2][lrA] = a.z; sA[lcA + 3][lrA] = a.w;
#pragma unroll
        for (int i = 0; i < 2; ++i) {
            int lin = tid + i * 256;
            int ml = lin >> 5, j4 = (lin & 31) << 2;
            float4 v = make_float4(0.f, 0.f, 0.f, 0.f);
            if (k0 + ml < MM)
                v = *(const float4*)(Bb + (size_t)(k0 + ml) * (2 * DD) + j0 + j4);
            *(float4*)&sB[ml][j4] = v;
        }
        __syncthreads();
#pragma unroll
        for (int k = 0; k < 16; ++k) {
            float4 af = *(const float4*)&sA[k][ty << 2];
            float4 b0 = *(const float4*)&sB[k][tx << 3];
            float4 b1 = *(const float4*)&sB[k][(tx << 3) + 4];
            float ar[4] = {af.x, af.y, af.z, af.w};
            float br[8] = {b0.x, b0.y, b0.z, b0.w, b1.x, b1.y, b1.z, b1.w};
#pragma unroll
            for (int r = 0; r < 4; ++r)
#pragma unroll
                for (int c = 0; c < 8; ++c)
                    acc[r][c] = fmaf(ar[r], br[c], acc[r][c]);
        }
        __syncthreads();
    }
    const int d0 = (j0 >> 1) + (tx << 2);
#pragma unroll
    for (int r = 0; r < 4; ++r) {
        int n = n0 + (ty << 2) + r;
        if (n >= NN) continue;
        float4 sq = *(const float4*)(g_SQ + ((size_t)b * NN + n) * DD + d0);
        float sqa[4] = {sq.x, sq.y, sq.z, sq.w};
        float4 o;
        float* po = &o.x;
#pragma unroll
        for (int u = 0; u < 4; ++u) {
            float num = acc[r][2 * u], den = acc[r][2 * u + 1];
            float w = num / den;
            if (!isfinite(w)) w = 0.f;    // nan_to_num
            po[u] = sqa[u] * w;
        }
        *(float4*)(g_AAFM + ((size_t)b * NN + n) * DD + d0) = o;
    }
}

// ---------------------------------------------------------------------------
// score: S(n,m) = 10*tanh(aafm@jobs^T/16 - a2*ls*cost) + mask
// ---------------------------------------------------------------------------
__global__ __launch_bounds__(256) void score_kernel(
    const float* __restrict__ jobs, const float* __restrict__ cost,
    const float* __restrict__ mask, const float* __restrict__ alpha2,
    const float* __restrict__ log_scale)
{
    __shared__ float sA[16][68];  // [d][n]
    __shared__ float sB[16][68];  // [d][m]
    const int b  = blockIdx.z;
    const int n0 = blockIdx.y * 64;
    const int m0 = blockIdx.x * 64;
    const int tid = threadIdx.x;
    const int tx = tid & 15, ty = tid >> 4;
    const int lr = tid >> 2, lc = (tid & 3) << 2;
    const float* Ab = g_AAFM + (size_t)b * NN * DD;
    const float* Bb = jobs   + (size_t)b * MM * DD;
    float acc[4][4] = {};

    for (int k0 = 0; k0 < DD; k0 += 16) {
        float4 a = make_float4(0.f, 0.f, 0.f, 0.f);
        if (n0 + lr < NN) a = *(const float4*)(Ab + (size_t)(n0 + lr) * DD + k0 + lc);
        sA[lc + 0][lr] = a.x; sA[lc + 1][lr] = a.y;
        sA[lc + 2][lr] = a.z; sA[lc + 3][lr] = a.w;
        float4 bj = make_float4(0.f, 0.f, 0.f, 0.f);
        if (m0 + lr < MM) bj = *(const float4*)(Bb + (size_t)(m0 + lr) * DD + k0 + lc);
        sB[lc + 0][lr] = bj.x; sB[lc + 1][lr] = bj.y;
        sB[lc + 2][lr] = bj.z; sB[lc + 3][lr] = bj.w;
        __syncthreads();
#pragma unroll
        for (int k = 0; k < 16; ++k) {
            float4 af = *(const float4*)&sA[k][ty << 2];
            float4 bf = *(const float4*)&sB[k][tx << 2];
            float ar[4] = {af.x, af.y, af.z, af.w};
            float br[4] = {bf.x, bf.y, bf.z, bf.w};
#pragma unroll
            for (int r = 0; r < 4; ++r)
#pragma unroll
                for (int c = 0; c < 4; ++c)
                    acc[r][c] = fmaf(ar[r], br[c], acc[r][c]);
        }
        __syncthreads();
    }
    const float c2 = alpha2[0] * log_scale[0];
    const int m = m0 + (tx << 2);
#pragma unroll
    for (int r = 0; r < 4; ++r) {
        int n = n0 + (ty << 2) + r;
        if (n >= NN || m >= MM) continue;
        const size_t off = ((size_t)b * NN + n) * MM + m;
        float4 cc = *(const float4*)(cost + off);
        float4 mk = *(const float4*)(mask + off);
        float4 o;
        o.x = 10.f * tanhf(fmaf(acc[r][0], 0.0625f, -c2 * cc.x)) + mk.x;
        o.y = 10.f * tanhf(fmaf(acc[r][1], 0.0625f, -c2 * cc.y)) + mk.y;
        o.z = 10.f * tanhf(fmaf(acc[r][2], 0.0625f, -c2 * cc.z)) + mk.z;
        o.w = 10.f * tanhf(fmaf(acc[r][3], 0.0625f, -c2 * cc.w)) + mk.w;
        *(float4*)(g_S + off) = o;
    }
}

// ---------------------------------------------------------------------------
// softmax over last dim (M=500), one block per (b,n) row
// ---------------------------------------------------------------------------
__global__ __launch_bounds__(256) void softmax_kernel(float* __restrict__ out)
{
    const int b = blockIdx.y, n = blockIdx.x;
    const float* row  = g_S + ((size_t)b * NN + n) * MM;
    float* orow = out + ((size_t)b * NN + n) * MM;
    __shared__ float red[256];
    const int tid = threadIdx.x;
    float v0 = row[tid];
    float v1 = (tid + 256 < MM) ? row[tid + 256] : -INFINITY;
    red[tid] = fmaxf(v0, v1);
    __syncthreads();
    for (int s = 128; s > 0; s >>= 1) {
        if (tid < s) red[tid] = fmaxf(red[tid], red[tid + s]);
        __syncthreads();
    }
    const float mx = red[0];
    __syncthreads();
    float e0 = expf(v0 - mx);
    float e1 = (tid + 256 < MM) ? expf(v1 - mx) : 0.f;
    red[tid] = e0 + e1;
    __syncthreads();
    for (int s = 128; s > 0; s >>= 1) {
        if (tid < s) red[tid] += red[tid + s];
        __syncthreads();
    }
    const float inv = 1.f / red[0];
    orow[tid] = e0 * inv;
    if (tid + 256 < MM) orow[tid + 256] = e1 * inv;
}

// ---------------------------------------------------------------------------
extern "C" void kernel_launch(void* const* d_in, const int* in_sizes, int n_in,
                              void* d_out, int out_size)
{
    const float* q0        = (const float*)d_in[0];
    const float* jobs      = (const float*)d_in[1];
    const float* q1        = (const float*)d_in[2];
    const float* cost      = (const float*)d_in[3];
    const float* log_scale = (const float*)d_in[4];
    const float* mask      = (const float*)d_in[5];
    const float* Wq0       = (const float*)d_in[6];
    const float* Wq1       = (const float*)d_in[7];
    const float* Wk        = (const float*)d_in[8];
    const float* Wv        = (const float*)d_in[9];
    const float* a1        = (const float*)d_in[10];
    const float* a2        = (const float*)d_in[11];
    float* out = (float*)d_out;

    dim3 blk(256);
    proj_kv_kernel<<<dim3(4, 8, BB), blk>>>(jobs, Wk, Wv);
    proj_q_kernel<<<dim3(4, 8, BB), blk>>>(q0, Wq0, q1, Wq1);
    eb_kernel<<<2048, 256>>>(cost, mask, a1, log_scale);
    aafm_kernel<<<dim3(4, 8, BB), blk>>>();
    score_kernel<<<dim3(8, 8, BB), blk>>>(jobs, cost, mask, a2, log_scale);
    softmax_kernel<<<dim3(NN, BB), blk>>>(out);
}

// round 4
// speedup vs baseline: 1.1476x; 1.1476x over previous
#include <cuda_runtime.h>
#include <math.h>

#define BB 32
#define NN 500
#define MM 500
#define DD 256

// Scratch (allocation-free: __device__ globals)
static __device__ float g_KE2[(size_t)BB * MM * 2 * DD];  // [b][m][2d]: even=exp(k)*v, odd=exp(k)
static __device__ float g_SQ [(size_t)BB * NN * DD];      // sigmoid(q0@Wq0^T + q1@Wq1^T)
static __device__ float g_EB [(size_t)BB * NN * MM];      // exp(-a1*ls*cost + mask)
static __device__ float g_AAFM[(size_t)BB * NN * DD];     // sigmoid(q) * num/den
static __device__ float g_S  [(size_t)BB * NN * MM];      // pre-softmax logits

// ===========================================================================
// Shared GEMM building blocks: 128x128 tile, 256 threads, 8x8 micro-tile,
// k-tile = 16, double-buffered smem (stride 132 words).
// Micro fragment layout: rows {ty*4..+3, 64+ty*4..+3}, cols {tx*4..+3, 64+tx*4..+3}
// ===========================================================================

// Transposed loader: global [row][k] row-major -> regs (2 float4 along k)
__device__ __forceinline__ void ldT(const float* __restrict__ G, int row0,
                                    int rowMax, int ld, int k0, int kMax,
                                    int tid, float4 v[2])
{
#pragma unroll
    for (int i = 0; i < 2; ++i) {
        int f = tid + i * 256;
        int r = f >> 2, kq = (f & 3) << 2;
        int gr = row0 + r, gk = k0 + kq;
        v[i] = make_float4(0.f, 0.f, 0.f, 0.f);
        if (gr < rowMax && gk < kMax)
            v[i] = *(const float4*)(G + (size_t)gr * ld + gk);
    }
}

// Store transposed regs into smem tile [k][rowsTile]
__device__ __forceinline__ void stT(float (*s)[132], int tid, const float4 v[2])
{
#pragma unroll
    for (int i = 0; i < 2; ++i) {
        int f = tid + i * 256;
        int r = f >> 2, kq = (f & 3) << 2;
        s[kq + 0][r] = v[i].x; s[kq + 1][r] = v[i].y;
        s[kq + 2][r] = v[i].z; s[kq + 3][r] = v[i].w;
    }
}

// Direct loader: global [k][col] row-major (col contiguous) -> regs
__device__ __forceinline__ void ldD(const float* __restrict__ G, int k0,
                                    int kMax, int ld, int col0, int tid,
                                    float4 v[2])
{
#pragma unroll
    for (int i = 0; i < 2; ++i) {
        int f = tid + i * 256;
        int kl = f >> 5, j4 = (f & 31) << 2;
        v[i] = make_float4(0.f, 0.f, 0.f, 0.f);
        if (k0 + kl < kMax)
            v[i] = *(const float4*)(G + (size_t)(k0 + kl) * ld + col0 + j4);
    }
}

__device__ __forceinline__ void stD(float (*s)[132], int tid, const float4 v[2])
{
#pragma unroll
    for (int i = 0; i < 2; ++i) {
        int f = tid + i * 256;
        int kl = f >> 5, j4 = (f & 31) << 2;
        *(float4*)&s[kl][j4] = v[i];
    }
}

// Interleaved Wk/Wv loader for proj_kv: B col j -> (j even ? Wk : Wv)[j/2][k]
__device__ __forceinline__ void ldKV(const float* __restrict__ Wk,
                                     const float* __restrict__ Wv,
                                     int j0, int k0, int tid, float4 v[2])
{
#pragma unroll
    for (int i = 0; i < 2; ++i) {
        int f = tid + i * 256;
        int j = f >> 2, kq = (f & 3) << 2;
        int jg = j0 + j;
        const float* W = (jg & 1) ? Wv : Wk;
        v[i] = *(const float4*)(W + (size_t)(jg >> 1) * DD + k0 + kq);
    }
}

// 16-deep k inner product on the 8x8 micro-tile
__device__ __forceinline__ void mma16(const float (*sA)[132],
                                      const float (*sB)[132],
                                      int tx, int ty, float acc[8][8])
{
#pragma unroll
    for (int k = 0; k < 16; ++k) {
        float4 a0 = *(const float4*)&sA[k][ty << 2];
        float4 a1 = *(const float4*)&sA[k][(ty << 2) + 64];
        float4 b0 = *(const float4*)&sB[k][tx << 2];
        float4 b1 = *(const float4*)&sB[k][(tx << 2) + 64];
        float ar[8] = {a0.x, a0.y, a0.z, a0.w, a1.x, a1.y, a1.z, a1.w};
        float br[8] = {b0.x, b0.y, b0.z, b0.w, b1.x, b1.y, b1.z, b1.w};
#pragma unroll
        for (int r = 0; r < 8; ++r)
#pragma unroll
            for (int c = 0; c < 8; ++c)
                acc[r][c] = fmaf(ar[r], br[c], acc[r][c]);
    }
}

// ===========================================================================
// proj_kv: [m][j] accumulate jobs@[Wk|Wv interleaved]^T, epilogue exp/pack
// ===========================================================================
__global__ __launch_bounds__(256, 2) void proj_kv_kernel(
    const float* __restrict__ jobs, const float* __restrict__ Wk,
    const float* __restrict__ Wv)
{
    __shared__ float sA[2][16][132];
    __shared__ float sB[2][16][132];
    const int b = blockIdx.z, m0 = blockIdx.y * 128, j0 = blockIdx.x * 128;
    const int tid = threadIdx.x, tx = tid & 15, ty = tid >> 4;
    const float* A = jobs + (size_t)b * MM * DD;
    float acc[8][8] = {};
    float4 vA[2], vB[2];
    const int T = DD / 16;  // 16

    ldT(A, m0, MM, DD, 0, DD, tid, vA);
    ldKV(Wk, Wv, j0, 0, tid, vB);
    stT(sA[0], tid, vA); stT(sB[0], tid, vB);
    __syncthreads();
    for (int t = 0; t < T; ++t) {
        int cur = t & 1;
        if (t + 1 < T) {
            ldT(A, m0, MM, DD, (t + 1) * 16, DD, tid, vA);
            ldKV(Wk, Wv, j0, (t + 1) * 16, tid, vB);
        }
        mma16(sA[cur], sB[cur], tx, ty, acc);
        if (t + 1 < T) { stT(sA[cur ^ 1], tid, vA); stT(sB[cur ^ 1], tid, vB); }
        __syncthreads();
    }
#pragma unroll
    for (int r = 0; r < 8; ++r) {
        int m = m0 + ((r < 4) ? (ty << 2) + r : 64 + (ty << 2) + (r - 4));
        if (m >= MM) continue;
        float* out = g_KE2 + ((size_t)b * MM + m) * (2 * DD);
#pragma unroll
        for (int h = 0; h < 2; ++h) {
            int jb = j0 + h * 64 + (tx << 2);
            float k0v = acc[r][h * 4 + 0], v0v = acc[r][h * 4 + 1];
            float k1v = acc[r][h * 4 + 2], v1v = acc[r][h * 4 + 3];
            float e0 = expf(k0v), e1 = expf(k1v);
            float4 o = make_float4(e0 * v0v, e0, e1 * v1v, e1);
            *(float4*)(out + jb) = o;
        }
    }
}

// ===========================================================================
// proj_q: q = q0@Wq0^T + q1@Wq1^T, epilogue sigmoid -> g_SQ
// ===========================================================================
__global__ __launch_bounds__(256, 2) void proj_q_kernel(
    const float* __restrict__ q0, const float* __restrict__ Wq0,
    const float* __restrict__ q1, const float* __restrict__ Wq1)
{
    __shared__ float sA[2][16][132];
    __shared__ float sB[2][16][132];
    const int b = blockIdx.z, n0 = blockIdx.y * 128, e0 = blockIdx.x * 128;
    const int tid = threadIdx.x, tx = tid & 15, ty = tid >> 4;
    const float* A0 = q0 + (size_t)b * NN * DD;
    const float* A1 = q1 + (size_t)b * NN * DD;
    float acc[8][8] = {};
    float4 vA[2], vB[2];
    const int T = 2 * DD / 16;  // 32 (two phases of 16)

    ldT(A0, n0, NN, DD, 0, DD, tid, vA);
    ldT(Wq0 + e0 * DD, 0, 128, DD, 0, DD, tid, vB);
    stT(sA[0], tid, vA); stT(sB[0], tid, vB);
    __syncthreads();
    for (int t = 0; t < T; ++t) {
        int cur = t & 1;
        if (t + 1 < T) {
            int tn = t + 1;
            const float* Ap = (tn < 16) ? A0 : A1;
            const float* Wp = (tn < 16) ? Wq0 : Wq1;
            int k0 = (tn & 15) * 16;
            ldT(Ap, n0, NN, DD, k0, DD, tid, vA);
            ldT(Wp + e0 * DD, 0, 128, DD, k0, DD, tid, vB);
        }
        mma16(sA[cur], sB[cur], tx, ty, acc);
        if (t + 1 < T) { stT(sA[cur ^ 1], tid, vA); stT(sB[cur ^ 1], tid, vB); }
        __syncthreads();
    }
#pragma unroll
    for (int r = 0; r < 8; ++r) {
        int n = n0 + ((r < 4) ? (ty << 2) + r : 64 + (ty << 2) + (r - 4));
        if (n >= NN) continue;
        float* out = g_SQ + ((size_t)b * NN + n) * DD;
#pragma unroll
        for (int h = 0; h < 2; ++h) {
            int eb = e0 + h * 64 + (tx << 2);
            float4 o;
            o.x = 1.f / (1.f + expf(-acc[r][h * 4 + 0]));
            o.y = 1.f / (1.f + expf(-acc[r][h * 4 + 1]));
            o.z = 1.f / (1.f + expf(-acc[r][h * 4 + 2]));
            o.w = 1.f / (1.f + expf(-acc[r][h * 4 + 3]));
            *(float4*)(out + eb) = o;
        }
    }
}

// ===========================================================================
// eb: exp_bias = exp(-a1*ls*cost + mask)
// ===========================================================================
__global__ void eb_kernel(const float* __restrict__ cost,
                          const float* __restrict__ mask,
                          const float* __restrict__ alpha1,
                          const float* __restrict__ log_scale)
{
    const float s1 = -alpha1[0] * log_scale[0];
    const size_t total4 = (size_t)BB * NN * MM / 4;
    const float4* c4 = (const float4*)cost;
    const float4* m4 = (const float4*)mask;
    float4* e4 = (float4*)g_EB;
    for (size_t i = (size_t)blockIdx.x * blockDim.x + threadIdx.x; i < total4;
         i += (size_t)gridDim.x * blockDim.x) {
        float4 c = c4[i], mk = m4[i];
        float4 r;
        r.x = expf(fmaf(s1, c.x, mk.x));
        r.y = expf(fmaf(s1, c.y, mk.y));
        r.z = expf(fmaf(s1, c.z, mk.z));
        r.w = expf(fmaf(s1, c.w, mk.w));
        e4[i] = r;
    }
}

// ===========================================================================
// aafm: [num|den](n,2d) = EB(n,m) @ KE2(m,2d); out = SQ * num/den
// ===========================================================================
__global__ __launch_bounds__(256, 2) void aafm_kernel()
{
    __shared__ float sA[2][16][132];
    __shared__ float sB[2][16][132];
    const int b = blockIdx.z, n0 = blockIdx.y * 128, j0 = blockIdx.x * 128;
    const int tid = threadIdx.x, tx = tid & 15, ty = tid >> 4;
    const float* EBb = g_EB + (size_t)b * NN * MM;
    const float* Bb = g_KE2 + (size_t)b * MM * (2 * DD);
    float acc[8][8] = {};
    float4 vA[2], vB[2];
    const int T = (MM + 15) / 16;  // 32

    ldT(EBb, n0, NN, MM, 0, MM, tid, vA);
    ldD(Bb, 0, MM, 2 * DD, j0, tid, vB);
    stT(sA[0], tid, vA); stD(sB[0], tid, vB);
    __syncthreads();
    for (int t = 0; t < T; ++t) {
        int cur = t & 1;
        if (t + 1 < T) {
            ldT(EBb, n0, NN, MM, (t + 1) * 16, MM, tid, vA);
            ldD(Bb, (t + 1) * 16, MM, 2 * DD, j0, tid, vB);
        }
        mma16(sA[cur], sB[cur], tx, ty, acc);
        if (t + 1 < T) { stT(sA[cur ^ 1], tid, vA); stD(sB[cur ^ 1], tid, vB); }
        __syncthreads();
    }
#pragma unroll
    for (int r = 0; r < 8; ++r) {
        int n = n0 + ((r < 4) ? (ty << 2) + r : 64 + (ty << 2) + (r - 4));
        if (n >= NN) continue;
        const float* sqrow = g_SQ + ((size_t)b * NN + n) * DD;
        float* arow = g_AAFM + ((size_t)b * NN + n) * DD;
#pragma unroll
        for (int h = 0; h < 2; ++h) {
            int jb = j0 + h * 64 + (tx << 2);
            int d0 = jb >> 1;
            float w0 = acc[r][h * 4 + 0] / acc[r][h * 4 + 1];
            float w1 = acc[r][h * 4 + 2] / acc[r][h * 4 + 3];
            if (!isfinite(w0)) w0 = 0.f;
            if (!isfinite(w1)) w1 = 0.f;
            float2 sq = *(const float2*)(sqrow + d0);
            float2 o = make_float2(sq.x * w0, sq.y * w1);
            *(float2*)(arow + d0) = o;
        }
    }
}

// ===========================================================================
// score: S(n,m) = 10*tanh(aafm@jobs^T/16 - a2*ls*cost) + mask
// ===========================================================================
__global__ __launch_bounds__(256, 2) void score_kernel(
    const float* __restrict__ jobs, const float* __restrict__ cost,
    const float* __restrict__ mask, const float* __restrict__ alpha2,
    const float* __restrict__ log_scale)
{
    __shared__ float sA[2][16][132];
    __shared__ float sB[2][16][132];
    const int b = blockIdx.z, n0 = blockIdx.y * 128, m0 = blockIdx.x * 128;
    const int tid = threadIdx.x, tx = tid & 15, ty = tid >> 4;
    const float* Ab = g_AAFM + (size_t)b * NN * DD;
    const float* Bb = jobs + (size_t)b * MM * DD;
    float acc[8][8] = {};
    float4 vA[2], vB[2];
    const int T = DD / 16;  // 16

    ldT(Ab, n0, NN, DD, 0, DD, tid, vA);
    ldT(Bb, m0, MM, DD, 0, DD, tid, vB);
    stT(sA[0], tid, vA); stT(sB[0], tid, vB);
    __syncthreads();
    for (int t = 0; t < T; ++t) {
        int cur = t & 1;
        if (t + 1 < T) {
            ldT(Ab, n0, NN, DD, (t + 1) * 16, DD, tid, vA);
            ldT(Bb, m0, MM, DD, (t + 1) * 16, DD, tid, vB);
        }
        mma16(sA[cur], sB[cur], tx, ty, acc);
        if (t + 1 < T) { stT(sA[cur ^ 1], tid, vA); stT(sB[cur ^ 1], tid, vB); }
        __syncthreads();
    }
    const float c2 = alpha2[0] * log_scale[0];
#pragma unroll
    for (int r = 0; r < 8; ++r) {
        int n = n0 + ((r < 4) ? (ty << 2) + r : 64 + (ty << 2) + (r - 4));
        if (n >= NN) continue;
#pragma unroll
        for (int h = 0; h < 2; ++h) {
            int mb = m0 + h * 64 + (tx << 2);
            if (mb >= MM) continue;
            const size_t off = ((size_t)b * NN + n) * MM + mb;
            float4 cc = *(const float4*)(cost + off);
            float4 mk = *(const float4*)(mask + off);
            float4 o;
            o.x = 10.f * tanhf(fmaf(acc[r][h * 4 + 0], 0.0625f, -c2 * cc.x)) + mk.x;
            o.y = 10.f * tanhf(fmaf(acc[r][h * 4 + 1], 0.0625f, -c2 * cc.y)) + mk.y;
            o.z = 10.f * tanhf(fmaf(acc[r][h * 4 + 2], 0.0625f, -c2 * cc.z)) + mk.z;
            o.w = 10.f * tanhf(fmaf(acc[r][h * 4 + 3], 0.0625f, -c2 * cc.w)) + mk.w;
            *(float4*)(g_S + off) = o;
        }
    }
}

// ===========================================================================
// softmax over last dim (M=500), one block per (b,n) row
// ===========================================================================
__global__ __launch_bounds__(256) void softmax_kernel(float* __restrict__ out)
{
    const int b = blockIdx.y, n = blockIdx.x;
    const float* row = g_S + ((size_t)b * NN + n) * MM;
    float* orow = out + ((size_t)b * NN + n) * MM;
    __shared__ float red[256];
    const int tid = threadIdx.x;
    float v0 = row[tid];
    float v1 = (tid + 256 < MM) ? row[tid + 256] : -INFINITY;
    red[tid] = fmaxf(v0, v1);
    __syncthreads();
    for (int s = 128; s > 0; s >>= 1) {
        if (tid < s) red[tid] = fmaxf(red[tid], red[tid + s]);
        __syncthreads();
    }
    const float mx = red[0];
    __syncthreads();
    float e0 = expf(v0 - mx);
    float e1 = (tid + 256 < MM) ? expf(v1 - mx) : 0.f;
    red[tid] = e0 + e1;
    __syncthreads();
    for (int s = 128; s > 0; s >>= 1) {
        if (tid < s) red[tid] += red[tid + s];
        __syncthreads();
    }
    const float inv = 1.f / red[0];
    orow[tid] = e0 * inv;
    if (tid + 256 < MM) orow[tid + 256] = e1 * inv;
}

// ---------------------------------------------------------------------------
extern "C" void kernel_launch(void* const* d_in, const int* in_sizes, int n_in,
                              void* d_out, int out_size)
{
    const float* q0        = (const float*)d_in[0];
    const float* jobs      = (const float*)d_in[1];
    const float* q1        = (const float*)d_in[2];
    const float* cost      = (const float*)d_in[3];
    const float* log_scale = (const float*)d_in[4];
    const float* mask      = (const float*)d_in[5];
    const float* Wq0       = (const float*)d_in[6];
    const float* Wq1       = (const float*)d_in[7];
    const float* Wk        = (const float*)d_in[8];
    const float* Wv        = (const float*)d_in[9];
    const float* a1        = (const float*)d_in[10];
    const float* a2        = (const float*)d_in[11];
    float* out = (float*)d_out;

    dim3 blk(256);
    proj_kv_kernel<<<dim3(4, 4, BB), blk>>>(jobs, Wk, Wv);
    proj_q_kernel<<<dim3(2, 4, BB), blk>>>(q0, Wq0, q1, Wq1);
    eb_kernel<<<1958, 256>>>(cost, mask, a1, log_scale);
    aafm_kernel<<<dim3(4, 4, BB), blk>>>();
    score_kernel<<<dim3(4, 4, BB), blk>>>(jobs, cost, mask, a2, log_scale);
    softmax_kernel<<<dim3(NN, BB), blk>>>(out);
}

// round 6
// speedup vs baseline: 1.6024x; 1.3963x over previous
#include <cuda_runtime.h>
#include <cuda_bf16.h>
#include <math.h>
#include <stdint.h>

#define BB 32
#define NN 500
#define MM 500
#define DD 256
#define NP 512
#define MP 512

#define LDS 72                  // smem row stride (bf16 elems), 144B
#define ABUF_B (128 * LDS * 2)  // 18432 B per tile buffer
#define SMEM_MMA (4 * ABUF_B)   // A0,A1,B0,B1 = 73728 B

typedef __nv_bfloat16 bf16;

// ---------------------------------------------------------------------------
// Scratch (allocation-free __device__ globals)
// ---------------------------------------------------------------------------
static __device__ bf16 g_EBh[(size_t)BB * NP * MP];  // exp_bias hi [b][n512][m512]
static __device__ bf16 g_EBl[(size_t)BB * NP * MP];  // exp_bias lo
static __device__ bf16 g_K2h[(size_t)BB * NP * MP];  // [b][j512][m512] j even: ek*v, odd: ek
static __device__ bf16 g_K2l[(size_t)BB * NP * MP];
static __device__ bf16 g_Jh [(size_t)BB * MP * DD];  // jobs hi [b][m512][d256]
static __device__ bf16 g_Jl [(size_t)BB * MP * DD];
static __device__ bf16 g_AFh[(size_t)BB * NP * DD];  // aafm hi [b][n512][d256]
static __device__ bf16 g_AFl[(size_t)BB * NP * DD];
static __device__ float g_SQ[(size_t)BB * NN * DD];  // sigmoid(q)
static __device__ float g_S [(size_t)BB * NN * MM];  // logits

// ---------------------------------------------------------------------------
// helpers
// ---------------------------------------------------------------------------
__device__ __forceinline__ uint32_t smem_u32(const void* p) {
    uint32_t a;
    asm("{ .reg .u64 t; cvta.to.shared.u64 t, %1; cvt.u32.u64 %0, t; }"
        : "=r"(a) : "l"(p));
    return a;
}

__device__ __forceinline__ void split2(float x, bf16& h, bf16& l) {
    h = __float2bfloat16(x);
    l = __float2bfloat16(x - __bfloat162float(h));
}

__device__ __forceinline__ void st_b162(bf16* p, bf16 a, bf16 b) {
    __nv_bfloat162 t; t.x = a; t.y = b;
    *(__nv_bfloat162*)p = t;
}

#define CP_ASYNC16(dst, src) \
    asm volatile("cp.async.cg.shared.global [%0], [%1], 16;" \
                 :: "r"(dst), "l"(src))
#define CP_COMMIT() asm volatile("cp.async.commit_group;" ::: "memory")
#define CP_WAIT(n)  asm volatile("cp.async.wait_group %0;" :: "n"(n) : "memory")

__device__ __forceinline__ void ldm4(uint32_t r[4], uint32_t addr) {
    asm volatile("ldmatrix.sync.aligned.m8n8.x4.shared.b16 {%0,%1,%2,%3}, [%4];"
                 : "=r"(r[0]), "=r"(r[1]), "=r"(r[2]), "=r"(r[3]) : "r"(addr));
}

__device__ __forceinline__ void mma16816(float c[4], const uint32_t a[4],
                                         const uint32_t b[2]) {
    asm volatile(
        "mma.sync.aligned.m16n8k16.row.col.f32.bf16.bf16.f32 "
        "{%0,%1,%2,%3}, {%4,%5,%6,%7}, {%8,%9}, {%0,%1,%2,%3};"
        : "+f"(c[0]), "+f"(c[1]), "+f"(c[2]), "+f"(c[3])
        : "r"(a[0]), "r"(a[1]), "r"(a[2]), "r"(a[3]), "r"(b[0]), "r"(b[1]));
}

// ---------------------------------------------------------------------------
// mma.sync GEMM core: CTA tile 128(M)x128(N), 8 warps (wm=wid&1 -> 64 rows,
// wn=wid>>1 -> 32 cols), K in 64-chunks, 3 split-phases: AhBh + AlBh + AhBl.
// A [M][ldA], B [N][ldB] row-major bf16 (TN). Double-buffered smem + cp.async.
// ---------------------------------------------------------------------------
__device__ __forceinline__ void mma_issue(uint32_t sb, int buf,
    const bf16* __restrict__ Ap, int ldA,
    const bf16* __restrict__ Bp, int ldB, int k0, int tid)
{
    const uint32_t abuf = sb + buf * ABUF_B;
    const uint32_t bbuf = sb + 2 * ABUF_B + buf * ABUF_B;
#pragma unroll
    for (int i = 0; i < 4; ++i) {
        int idx = tid + i * 256, row = idx >> 3, c8 = (idx & 7) * 8;
        CP_ASYNC16(abuf + (row * LDS + c8) * 2,
                   Ap + (size_t)row * ldA + k0 + c8);
    }
#pragma unroll
    for (int i = 0; i < 4; ++i) {
        int idx = tid + i * 256, row = idx >> 3, c8 = (idx & 7) * 8;
        CP_ASYNC16(bbuf + (row * LDS + c8) * 2,
                   Bp + (size_t)row * ldB + k0 + c8);
    }
    CP_COMMIT();
}

__device__ __forceinline__ void mma_compute(uint32_t sb, int buf, int wm,
                                            int wn, int lane,
                                            float acc[4][4][4])
{
    const uint32_t sA = sb + buf * ABUF_B;
    const uint32_t sB = sb + 2 * ABUF_B + buf * ABUF_B;
#pragma unroll
    for (int ks = 0; ks < 4; ++ks) {
        const int k0 = ks * 16;
        uint32_t a[4][4], bfr[4][2];
#pragma unroll
        for (int mt = 0; mt < 4; ++mt) {
            int row = wm * 64 + mt * 16 + (lane & 15);
            int col = k0 + ((lane >> 4) << 3);
            ldm4(a[mt], sA + (row * LDS + col) * 2);
        }
#pragma unroll
        for (int np = 0; np < 2; ++np) {
            int row = wn * 32 + np * 16 + (lane & 7) + ((lane >> 4) << 3);
            int col = k0 + ((lane >> 3) & 1) * 8;
            uint32_t r[4];
            ldm4(r, sB + (row * LDS + col) * 2);
            bfr[2 * np][0] = r[0]; bfr[2 * np][1] = r[1];
            bfr[2 * np + 1][0] = r[2]; bfr[2 * np + 1][1] = r[3];
        }
#pragma unroll
        for (int mt = 0; mt < 4; ++mt)
#pragma unroll
            for (int nt = 0; nt < 4; ++nt)
                mma16816(acc[mt][nt], a[mt], bfr[nt]);
    }
}

template <int KC>
__device__ __forceinline__ void mma_mainloop(uint32_t sb,
    const bf16* __restrict__ Ah, const bf16* __restrict__ Al, int ldA,
    const bf16* __restrict__ Bh, const bf16* __restrict__ Bl, int ldB,
    float acc[4][4][4])
{
    const int tid = threadIdx.x;
    const int lane = tid & 31, wid = tid >> 5, wm = wid & 1, wn = wid >> 1;
    const int TOT = 3 * KC;
    mma_issue(sb, 0, Ah, ldA, Bh, ldB, 0, tid);
    for (int it = 0; it < TOT; ++it) {
        if (it + 1 < TOT) {
            const int nxt = it + 1, phase = nxt / KC, k0 = (nxt % KC) * 64;
            const bf16* Ap = (phase == 1) ? Al : Ah;
            const bf16* Bp = (phase == 2) ? Bl : Bh;
            mma_issue(sb, nxt & 1, Ap, ldA, Bp, ldB, k0, tid);
            CP_WAIT(1);
        } else {
            CP_WAIT(0);
        }
        __syncthreads();
        mma_compute(sb, it & 1, wm, wn, lane, acc);
        __syncthreads();
    }
}

// ===========================================================================
// aafm_mma: D[n][j] = EB(n,m) @ K2(j,m)^T (K=512). Epilogue: w = num/den,
// out = sigmoid(q)*w, written bf16-split to AF for the score GEMM.
// grid (j-tile 4, n-tile 4, b)
// ===========================================================================
__global__ __launch_bounds__(256) void aafm_mma_kernel()
{
    extern __shared__ char smem[];
    const uint32_t sb = smem_u32(smem);
    const int b = blockIdx.z, n0 = blockIdx.y * 128, j0 = blockIdx.x * 128;
    const int tid = threadIdx.x, lane = tid & 31, wid = tid >> 5;
    const int wm = wid & 1, wn = wid >> 1;

    float acc[4][4][4] = {};
    const bf16* Ah = g_EBh + ((size_t)b * NP + n0) * MP;
    const bf16* Al = g_EBl + ((size_t)b * NP + n0) * MP;
    const bf16* Bh = g_K2h + ((size_t)b * NP + j0) * MP;
    const bf16* Bl = g_K2l + ((size_t)b * NP + j0) * MP;
    mma_mainloop<8>(sb, Ah, Al, MP, Bh, Bl, MP, acc);

#pragma unroll
    for (int mt = 0; mt < 4; ++mt)
#pragma unroll
        for (int half = 0; half < 2; ++half) {
            const int n = n0 + wm * 64 + mt * 16 + (lane >> 2) + half * 8;
            if (n >= NN) continue;
            const float* sqrow = g_SQ + ((size_t)b * NN + n) * DD;
            bf16* ah = g_AFh + ((size_t)b * NP + n) * DD;
            bf16* al = g_AFl + ((size_t)b * NP + n) * DD;
#pragma unroll
            for (int nt = 0; nt < 4; ++nt) {
                const int j = j0 + wn * 32 + nt * 8 + 2 * (lane & 3);
                const int d = j >> 1;
                const float num = acc[mt][nt][half * 2 + 0];
                const float den = acc[mt][nt][half * 2 + 1];
                float w = num / den;
                if (!isfinite(w)) w = 0.f;
                const float o = sqrow[d] * w;
                bf16 h, l;
                split2(o, h, l);
                ah[d] = h;
                al[d] = l;
            }
        }
}

// ===========================================================================
// score_mma: D[n][m] = AF(n,d) @ J(m,d)^T (K=256); epilogue tanh-clip -> g_S
// grid (m-tile 4, n-tile 4, b)
// ===========================================================================
__global__ __launch_bounds__(256) void score_mma_kernel(
    const float* __restrict__ cost, const float* __restrict__ mask,
    const float* __restrict__ alpha2, const float* __restrict__ log_scale)
{
    extern __shared__ char smem[];
    const uint32_t sb = smem_u32(smem);
    const int b = blockIdx.z, n0 = blockIdx.y * 128, m0 = blockIdx.x * 128;
    const int tid = threadIdx.x, lane = tid & 31, wid = tid >> 5;
    const int wm = wid & 1, wn = wid >> 1;

    float acc[4][4][4] = {};
    const bf16* Ah = g_AFh + ((size_t)b * NP + n0) * DD;
    const bf16* Al = g_AFl + ((size_t)b * NP + n0) * DD;
    const bf16* Bh = g_Jh + ((size_t)b * MP + m0) * DD;
    const bf16* Bl = g_Jl + ((size_t)b * MP + m0) * DD;
    mma_mainloop<4>(sb, Ah, Al, DD, Bh, Bl, DD, acc);

    const float c2 = alpha2[0] * log_scale[0];
#pragma unroll
    for (int mt = 0; mt < 4; ++mt)
#pragma unroll
        for (int half = 0; half < 2; ++half) {
            const int n = n0 + wm * 64 + mt * 16 + (lane >> 2) + half * 8;
            if (n >= NN) continue;
            const size_t rowoff = ((size_t)b * NN + n) * MM;
#pragma unroll
            for (int nt = 0; nt < 4; ++nt) {
                const int m = m0 + wn * 32 + nt * 8 + 2 * (lane & 3);
                if (m >= MM) continue;          // m even, so m+1 < MM too
                const float v0 = acc[mt][nt][half * 2 + 0];
                const float v1 = acc[mt][nt][half * 2 + 1];
                const float2 cc = *(const float2*)(cost + rowoff + m);
                const float2 mk = *(const float2*)(mask + rowoff + m);
                float2 o;
                o.x = 10.f * tanhf(fmaf(v0, 0.0625f, -c2 * cc.x)) + mk.x;
                o.y = 10.f * tanhf(fmaf(v1, 0.0625f, -c2 * cc.y)) + mk.y;
                *(float2*)(g_S + rowoff + m) = o;
            }
        }
}

// ===========================================================================
// SIMT building blocks (producer GEMMs) — proven R3 structure
// ===========================================================================
__device__ __forceinline__ void ldT(const float* __restrict__ G, int row0,
                                    int rowMax, int ld, int k0, int kMax,
                                    int tid, float4 v[2])
{
#pragma unroll
    for (int i = 0; i < 2; ++i) {
        int f = tid + i * 256;
        int r = f >> 2, kq = (f & 3) << 2;
        int gr = row0 + r, gk = k0 + kq;
        v[i] = make_float4(0.f, 0.f, 0.f, 0.f);
        if (gr < rowMax && gk < kMax)
            v[i] = *(const float4*)(G + (size_t)gr * ld + gk);
    }
}

__device__ __forceinline__ void stT(float (*s)[132], int tid, const float4 v[2])
{
#pragma unroll
    for (int i = 0; i < 2; ++i) {
        int f = tid + i * 256;
        int r = f >> 2, kq = (f & 3) << 2;
        s[kq + 0][r] = v[i].x; s[kq + 1][r] = v[i].y;
        s[kq + 2][r] = v[i].z; s[kq + 3][r] = v[i].w;
    }
}

__device__ __forceinline__ void ldKV(const float* __restrict__ Wk,
                                     const float* __restrict__ Wv,
                                     int j0, int k0, int tid, float4 v[2])
{
#pragma unroll
    for (int i = 0; i < 2; ++i) {
        int f = tid + i * 256;
        int j = f >> 2, kq = (f & 3) << 2;
        int jg = j0 + j;
        const float* W = (jg & 1) ? Wv : Wk;
        v[i] = *(const float4*)(W + (size_t)(jg >> 1) * DD + k0 + kq);
    }
}

__device__ __forceinline__ void mma16(const float (*sA)[132],
                                      const float (*sB)[132],
                                      int tx, int ty, float acc[8][8])
{
#pragma unroll
    for (int k = 0; k < 16; ++k) {
        float4 a0 = *(const float4*)&sA[k][ty << 2];
        float4 a1 = *(const float4*)&sA[k][(ty << 2) + 64];
        float4 b0 = *(const float4*)&sB[k][tx << 2];
        float4 b1 = *(const float4*)&sB[k][(tx << 2) + 64];
        float ar[8] = {a0.x, a0.y, a0.z, a0.w, a1.x, a1.y, a1.z, a1.w};
        float br[8] = {b0.x, b0.y, b0.z, b0.w, b1.x, b1.y, b1.z, b1.w};
#pragma unroll
        for (int r = 0; r < 8; ++r)
#pragma unroll
            for (int c = 0; c < 8; ++c)
                acc[r][c] = fmaf(ar[r], br[c], acc[r][c]);
    }
}

// ===========================================================================
// proj_kvT: K2[j][m] = (j even ? exp(k)*v : exp(k)), bf16-split, m padded 512
// ===========================================================================
__global__ __launch_bounds__(256, 2) void proj_kvT_kernel(
    const float* __restrict__ jobs, const float* __restrict__ Wk,
    const float* __restrict__ Wv)
{
    __shared__ float sA[2][16][132];
    __shared__ float sB[2][16][132];
    const int b = blockIdx.z, j0 = blockIdx.y * 128, m0 = blockIdx.x * 128;
    const int tid = threadIdx.x, tx = tid & 15, ty = tid >> 4;
    const float* Bb = jobs + (size_t)b * MM * DD;
    float acc[8][8] = {};
    float4 vA[2], vB[2];
    const int T = DD / 16;

    ldKV(Wk, Wv, j0, 0, tid, vA);
    ldT(Bb, m0, MM, DD, 0, DD, tid, vB);
    stT(sA[0], tid, vA); stT(sB[0], tid, vB);
    __syncthreads();
    for (int t = 0; t < T; ++t) {
        int cur = t & 1;
        if (t + 1 < T) {
            ldKV(Wk, Wv, j0, (t + 1) * 16, tid, vA);
            ldT(Bb, m0, MM, DD, (t + 1) * 16, DD, tid, vB);
        }
        mma16(sA[cur], sB[cur], tx, ty, acc);
        if (t + 1 < T) { stT(sA[cur ^ 1], tid, vA); stT(sB[cur ^ 1], tid, vB); }
        __syncthreads();
    }
#pragma unroll
    for (int h = 0; h < 2; ++h)
#pragma unroll
        for (int p = 0; p < 2; ++p) {
            const int rk = h * 4 + p * 2, rv = rk + 1;
            const int j = j0 + h * 64 + (ty << 2) + p * 2;
            bf16* he = g_K2h + ((size_t)b * NP + j) * MP;
            bf16* le = g_K2l + ((size_t)b * NP + j) * MP;
            bf16* ho = he + MP;
            bf16* lo_ = le + MP;
#pragma unroll
            for (int ch = 0; ch < 2; ++ch) {
                const int mb = m0 + ch * 64 + (tx << 2);
                bf16 vh[4], vl[4], eh[4], el[4];
#pragma unroll
                for (int cc = 0; cc < 4; ++cc) {
                    float ek = expf(acc[rk][ch * 4 + cc]);
                    float kv = ek * acc[rv][ch * 4 + cc];
                    if (mb + cc >= MM) { ek = 0.f; kv = 0.f; }
                    split2(kv, vh[cc], vl[cc]);
                    split2(ek, eh[cc], el[cc]);
                }
                st_b162(he + mb, vh[0], vh[1]); st_b162(he + mb + 2, vh[2], vh[3]);
                st_b162(le + mb, vl[0], vl[1]); st_b162(le + mb + 2, vl[2], vl[3]);
                st_b162(ho + mb, eh[0], eh[1]); st_b162(ho + mb + 2, eh[2], eh[3]);
                st_b162(lo_ + mb, el[0], el[1]); st_b162(lo_ + mb + 2, el[2], el[3]);
            }
        }
}

// ===========================================================================
// proj_q: q = q0@Wq0^T + q1@Wq1^T -> sigmoid -> g_SQ (fp32)
// ===========================================================================
__global__ __launch_bounds__(256, 2) void proj_q_kernel(
    const float* __restrict__ q0, const float* __restrict__ Wq0,
    const float* __restrict__ q1, const float* __restrict__ Wq1)
{
    __shared__ float sA[2][16][132];
    __shared__ float sB[2][16][132];
    const int b = blockIdx.z, n0 = blockIdx.y * 128, e0 = blockIdx.x * 128;
    const int tid = threadIdx.x, tx = tid & 15, ty = tid >> 4;
    const float* A0 = q0 + (size_t)b * NN * DD;
    const float* A1 = q1 + (size_t)b * NN * DD;
    float acc[8][8] = {};
    float4 vA[2], vB[2];
    const int T = 2 * DD / 16;

    ldT(A0, n0, NN, DD, 0, DD, tid, vA);
    ldT(Wq0 + e0 * DD, 0, 128, DD, 0, DD, tid, vB);
    stT(sA[0], tid, vA); stT(sB[0], tid, vB);
    __syncthreads();
    for (int t = 0; t < T; ++t) {
        int cur = t & 1;
        if (t + 1 < T) {
            int tn = t + 1;
            const float* Ap = (tn < 16) ? A0 : A1;
            const float* Wp = (tn < 16) ? Wq0 : Wq1;
            int k0 = (tn & 15) * 16;
            ldT(Ap, n0, NN, DD, k0, DD, tid, vA);
            ldT(Wp + e0 * DD, 0, 128, DD, k0, DD, tid, vB);
        }
        mma16(sA[cur], sB[cur], tx, ty, acc);
        if (t + 1 < T) { stT(sA[cur ^ 1], tid, vA); stT(sB[cur ^ 1], tid, vB); }
        __syncthreads();
    }
#pragma unroll
    for (int r = 0; r < 8; ++r) {
        int n = n0 + ((r < 4) ? (ty << 2) + r : 64 + (ty << 2) + (r - 4));
        if (n >= NN) continue;
        float* out = g_SQ + ((size_t)b * NN + n) * DD;
#pragma unroll
        for (int h = 0; h < 2; ++h) {
            int eb = e0 + h * 64 + (tx << 2);
            float4 o;
            o.x = 1.f / (1.f + expf(-acc[r][h * 4 + 0]));
            o.y = 1.f / (1.f + expf(-acc[r][h * 4 + 1]));
            o.z = 1.f / (1.f + expf(-acc[r][h * 4 + 2]));
            o.w = 1.f / (1.f + expf(-acc[r][h * 4 + 3]));
            *(float4*)(out + eb) = o;
        }
    }
}

// ===========================================================================
// eb_split: EB = exp(-a1*ls*cost + mask), padded [512][512], bf16 hi/lo
// ===========================================================================
__global__ __launch_bounds__(256) void eb_split_kernel(
    const float* __restrict__ cost, const float* __restrict__ mask,
    const float* __restrict__ alpha1, const float* __restrict__ log_scale)
{
    const float s1 = -alpha1[0] * log_scale[0];
    const int i = blockIdx.x * 256 + threadIdx.x;  // [0, 32*512*128)
    const int m4 = (i & 127) << 2;
    const int n = (i >> 7) & 511;
    const int b = i >> 16;
    bf16 h[4], l[4];
    const size_t crow = ((size_t)b * NN + n) * MM;
#pragma unroll
    for (int t = 0; t < 4; ++t) {
        int m = m4 + t;
        float x = 0.f;
        if (n < NN && m < MM)
            x = expf(fmaf(s1, cost[crow + m], mask[crow + m]));
        split2(x, h[t], l[t]);
    }
    const size_t o = ((size_t)b * NP + n) * MP + m4;
    st_b162(g_EBh + o, h[0], h[1]); st_b162(g_EBh + o + 2, h[2], h[3]);
    st_b162(g_EBl + o, l[0], l[1]); st_b162(g_EBl + o + 2, l[2], l[3]);
}

// ===========================================================================
// jobs_split: bf16 hi/lo of encoded_jobs, rows padded to 512 with zeros
// ===========================================================================
__global__ __launch_bounds__(256) void jobs_split_kernel(
    const float* __restrict__ jobs)
{
    const int i = blockIdx.x * 256 + threadIdx.x;  // [0, 32*512*64)
    const int c4 = (i & 63) << 2;
    const int m = (i >> 6) & 511;
    const int b = i >> 15;
    bf16 h[4], l[4];
#pragma unroll
    for (int t = 0; t < 4; ++t) {
        float x = (m < MM) ? jobs[((size_t)b * MM + m) * DD + c4 + t] : 0.f;
        split2(x, h[t], l[t]);
    }
    const size_t o = ((size_t)b * MP + m) * DD + c4;
    st_b162(g_Jh + o, h[0], h[1]); st_b162(g_Jh + o + 2, h[2], h[3]);
    st_b162(g_Jl + o, l[0], l[1]); st_b162(g_Jl + o + 2, l[2], l[3]);
}

// ===========================================================================
// softmax over last dim (M=500), one block per (b,n) row
// ===========================================================================
__global__ __launch_bounds__(256) void softmax_kernel(float* __restrict__ out)
{
    const int b = blockIdx.y, n = blockIdx.x;
    const float* row = g_S + ((size_t)b * NN + n) * MM;
    float* orow = out + ((size_t)b * NN + n) * MM;
    __shared__ float red[256];
    const int tid = threadIdx.x;
    float v0 = row[tid];
    float v1 = (tid + 256 < MM) ? row[tid + 256] : -INFINITY;
    red[tid] = fmaxf(v0, v1);
    __syncthreads();
    for (int s = 128; s > 0; s >>= 1) {
        if (tid < s) red[tid] = fmaxf(red[tid], red[tid + s]);
        __syncthreads();
    }
    const float mx = red[0];
    __syncthreads();
    float e0 = expf(v0 - mx);
    float e1 = (tid + 256 < MM) ? expf(v1 - mx) : 0.f;
    red[tid] = e0 + e1;
    __syncthreads();
    for (int s = 128; s > 0; s >>= 1) {
        if (tid < s) red[tid] += red[tid + s];
        __syncthreads();
    }
    const float inv = 1.f / red[0];
    orow[tid] = e0 * inv;
    if (tid + 256 < MM) orow[tid + 256] = e1 * inv;
}

// ---------------------------------------------------------------------------
extern "C" void kernel_launch(void* const* d_in, const int* in_sizes, int n_in,
                              void* d_out, int out_size)
{
    const float* q0        = (const float*)d_in[0];
    const float* jobs      = (const float*)d_in[1];
    const float* q1        = (const float*)d_in[2];
    const float* cost      = (const float*)d_in[3];
    const float* log_scale = (const float*)d_in[4];
    const float* mask      = (const float*)d_in[5];
    const float* Wq0       = (const float*)d_in[6];
    const float* Wq1       = (const float*)d_in[7];
    const float* Wk        = (const float*)d_in[8];
    const float* Wv        = (const float*)d_in[9];
    const float* a1        = (const float*)d_in[10];
    const float* a2        = (const float*)d_in[11];
    float* out = (float*)d_out;

    cudaFuncSetAttribute(aafm_mma_kernel,
                         cudaFuncAttributeMaxDynamicSharedMemorySize, SMEM_MMA);
    cudaFuncSetAttribute(score_mma_kernel,
                         cudaFuncAttributeMaxDynamicSharedMemorySize, SMEM_MMA);

    dim3 blk(256);
    eb_split_kernel<<<8192, blk>>>(cost, mask, a1, log_scale);
    jobs_split_kernel<<<4096, blk>>>(jobs);
    proj_kvT_kernel<<<dim3(4, 4, BB), blk>>>(jobs, Wk, Wv);
    proj_q_kernel<<<dim3(2, 4, BB), blk>>>(q0, Wq0, q1, Wq1);
    aafm_mma_kernel<<<dim3(4, 4, BB), blk, SMEM_MMA>>>();
    score_mma_kernel<<<dim3(4, 4, BB), blk, SMEM_MMA>>>(cost, mask, a2, log_scale);
    softmax_kernel<<<dim3(NN, BB), blk>>>(out);
}

// round 9
// speedup vs baseline: 1.9773x; 1.2340x over previous
#include <cuda_runtime.h>
#include <cuda_bf16.h>
#include <math.h>
#include <stdint.h>

#define BB 32
#define NN 500
#define MM 500
#define DD 256
#define NP 512
#define MP 512

#define LDS 72                  // smem row stride (bf16 elems), 144B
#define ABUF_B (128 * LDS * 2)  // 18432 B per tile buffer
#define SMEM_MMA (4 * ABUF_B)   // A0,A1,B0,B1 = 73728 B

typedef __nv_bfloat16 bf16;

// ---------------------------------------------------------------------------
// Scratch (allocation-free __device__ globals)
// ---------------------------------------------------------------------------
static __device__ bf16 g_EBh[(size_t)BB * NP * MP];  // exp_bias hi [b][n512][m512]
static __device__ bf16 g_EBl[(size_t)BB * NP * MP];
static __device__ bf16 g_K2h[(size_t)BB * NP * MP];  // [b][j512][m512] j even: ek*v, odd: ek
static __device__ bf16 g_K2l[(size_t)BB * NP * MP];
static __device__ bf16 g_Jh [(size_t)BB * MP * DD];  // jobs  [b][m512][d256]
static __device__ bf16 g_Jl [(size_t)BB * MP * DD];
static __device__ bf16 g_Q0h[(size_t)BB * NP * DD];  // q0    [b][n512][d256]
static __device__ bf16 g_Q0l[(size_t)BB * NP * DD];
static __device__ bf16 g_Q1h[(size_t)BB * NP * DD];  // q1
static __device__ bf16 g_Q1l[(size_t)BB * NP * DD];
static __device__ bf16 g_AFh[(size_t)BB * NP * DD];  // aafm  [b][n512][d256]
static __device__ bf16 g_AFl[(size_t)BB * NP * DD];
static __device__ bf16 g_W0h[DD * DD];               // Wq0
static __device__ bf16 g_W0l[DD * DD];
static __device__ bf16 g_W1h[DD * DD];               // Wq1
static __device__ bf16 g_W1l[DD * DD];
static __device__ bf16 g_WKVh[2 * DD * DD];          // interleaved [2e]=Wk[e], [2e+1]=Wv[e]
static __device__ bf16 g_WKVl[2 * DD * DD];
static __device__ float g_SQ[(size_t)BB * NN * DD];  // sigmoid(q)
static __device__ float g_S [(size_t)BB * NN * MM];  // logits

// ---------------------------------------------------------------------------
// helpers
// ---------------------------------------------------------------------------
__device__ __forceinline__ uint32_t smem_u32(const void* p) {
    uint32_t a;
    asm("{ .reg .u64 t; cvta.to.shared.u64 t, %1; cvt.u32.u64 %0, t; }"
        : "=r"(a) : "l"(p));
    return a;
}

__device__ __forceinline__ void split2(float x, bf16& h, bf16& l) {
    h = __float2bfloat16(x);
    l = __float2bfloat16(x - __bfloat162float(h));
}

__device__ __forceinline__ void st_b162(bf16* p, bf16 a, bf16 b) {
    __nv_bfloat162 t; t.x = a; t.y = b;
    *(__nv_bfloat162*)p = t;
}

#define CP_ASYNC16(dst, src) \
    asm volatile("cp.async.cg.shared.global [%0], [%1], 16;" \
                 :: "r"(dst), "l"(src))
#define CP_COMMIT() asm volatile("cp.async.commit_group;" ::: "memory")
#define CP_WAIT(n)  asm volatile("cp.async.wait_group %0;" :: "n"(n) : "memory")

__device__ __forceinline__ void ldm4(uint32_t r[4], uint32_t addr) {
    asm volatile("ldmatrix.sync.aligned.m8n8.x4.shared.b16 {%0,%1,%2,%3}, [%4];"
                 : "=r"(r[0]), "=r"(r[1]), "=r"(r[2]), "=r"(r[3]) : "r"(addr));
}

__device__ __forceinline__ void mma16816(float c[4], const uint32_t a[4],
                                         const uint32_t b[2]) {
    asm volatile(
        "mma.sync.aligned.m16n8k16.row.col.f32.bf16.bf16.f32 "
        "{%0,%1,%2,%3}, {%4,%5,%6,%7}, {%8,%9}, {%0,%1,%2,%3};"
        : "+f"(c[0]), "+f"(c[1]), "+f"(c[2]), "+f"(c[3])
        : "r"(a[0]), "r"(a[1]), "r"(a[2]), "r"(a[3]), "r"(b[0]), "r"(b[1]));
}

// ---------------------------------------------------------------------------
// mma.sync GEMM core: CTA tile 128(M)x128(N), 8 warps (wm=wid&1 -> 64 rows,
// wn=wid>>1 -> 32 cols). P phases of KC 64-wide K chunks; phase p multiplies
// Aps[p] x Bps[p] (bf16-split scheme handled by the phase pointer lists).
// ---------------------------------------------------------------------------
__device__ __forceinline__ void mma_issue(uint32_t sb, int buf,
    const bf16* __restrict__ Ap, int ldA,
    const bf16* __restrict__ Bp, int ldB, int k0, int tid)
{
    const uint32_t abuf = sb + buf * ABUF_B;
    const uint32_t bbuf = sb + 2 * ABUF_B + buf * ABUF_B;
#pragma unroll
    for (int i = 0; i < 4; ++i) {
        int idx = tid + i * 256, row = idx >> 3, c8 = (idx & 7) * 8;
        CP_ASYNC16(abuf + (row * LDS + c8) * 2,
                   Ap + (size_t)row * ldA + k0 + c8);
    }
#pragma unroll
    for (int i = 0; i < 4; ++i) {
        int idx = tid + i * 256, row = idx >> 3, c8 = (idx & 7) * 8;
        CP_ASYNC16(bbuf + (row * LDS + c8) * 2,
                   Bp + (size_t)row * ldB + k0 + c8);
    }
    CP_COMMIT();
}

__device__ __forceinline__ void mma_compute(uint32_t sb, int buf, int wm,
                                            int wn, int lane,
                                            float acc[4][4][4])
{
    const uint32_t sA = sb + buf * ABUF_B;
    const uint32_t sB = sb + 2 * ABUF_B + buf * ABUF_B;
#pragma unroll
    for (int ks = 0; ks < 4; ++ks) {
        const int k0 = ks * 16;
        uint32_t a[4][4], bfr[4][2];
#pragma unroll
        for (int mt = 0; mt < 4; ++mt) {
            int row = wm * 64 + mt * 16 + (lane & 15);
            int col = k0 + ((lane >> 4) << 3);
            ldm4(a[mt], sA + (row * LDS + col) * 2);
        }
#pragma unroll
        for (int np = 0; np < 2; ++np) {
            int row = wn * 32 + np * 16 + (lane & 7) + ((lane >> 4) << 3);
            int col = k0 + ((lane >> 3) & 1) * 8;
            uint32_t r[4];
            ldm4(r, sB + (row * LDS + col) * 2);
            bfr[2 * np][0] = r[0]; bfr[2 * np][1] = r[1];
            bfr[2 * np + 1][0] = r[2]; bfr[2 * np + 1][1] = r[3];
        }
#pragma unroll
        for (int mt = 0; mt < 4; ++mt)
#pragma unroll
            for (int nt = 0; nt < 4; ++nt)
                mma16816(acc[mt][nt], a[mt], bfr[nt]);
    }
}

template <int P, int KC>
__device__ __forceinline__ void mma_mainloop(uint32_t sb,
    const bf16* const Aps[P], int ldA,
    const bf16* const Bps[P], int ldB,
    float acc[4][4][4])
{
    const int tid = threadIdx.x;
    const int lane = tid & 31, wid = tid >> 5, wm = wid & 1, wn = wid >> 1;
    const int TOT = P * KC;
    mma_issue(sb, 0, Aps[0], ldA, Bps[0], ldB, 0, tid);
    for (int it = 0; it < TOT; ++it) {
        if (it + 1 < TOT) {
            const int nxt = it + 1, ph = nxt / KC, k0 = (nxt % KC) * 64;
            mma_issue(sb, nxt & 1, Aps[ph], ldA, Bps[ph], ldB, k0, tid);
            CP_WAIT(1);
        } else {
            CP_WAIT(0);
        }
        __syncthreads();
        mma_compute(sb, it & 1, wm, wn, lane, acc);
        __syncthreads();
    }
}

// ===========================================================================
// aafm_mma: D[n][j] = EB(n,m) @ K2(j,m)^T (K=512). Epilogue: w = num/den,
// out = sigmoid(q)*w, bf16-split -> AF.  grid (j 4, n 4, b)
// ===========================================================================
__global__ __launch_bounds__(256) void aafm_mma_kernel()
{
    extern __shared__ char smem[];
    const uint32_t sb = smem_u32(smem);
    const int b = blockIdx.z, n0 = blockIdx.y * 128, j0 = blockIdx.x * 128;
    const int tid = threadIdx.x, lane = tid & 31, wid = tid >> 5;
    const int wm = wid & 1, wn = wid >> 1;

    float acc[4][4][4] = {};
    const bf16* Ah = g_EBh + ((size_t)b * NP + n0) * MP;
    const bf16* Al = g_EBl + ((size_t)b * NP + n0) * MP;
    const bf16* Bh = g_K2h + ((size_t)b * NP + j0) * MP;
    const bf16* Bl = g_K2l + ((size_t)b * NP + j0) * MP;
    const bf16* Aps[3] = {Ah, Al, Ah};
    const bf16* Bps[3] = {Bh, Bh, Bl};
    mma_mainloop<3, 8>(sb, Aps, MP, Bps, MP, acc);

#pragma unroll
    for (int mt = 0; mt < 4; ++mt)
#pragma unroll
        for (int half = 0; half < 2; ++half) {
            const int n = n0 + wm * 64 + mt * 16 + (lane >> 2) + half * 8;
            if (n >= NN) continue;
            const float* sqrow = g_SQ + ((size_t)b * NN + n) * DD;
            bf16* ah = g_AFh + ((size_t)b * NP + n) * DD;
            bf16* al = g_AFl + ((size_t)b * NP + n) * DD;
#pragma unroll
            for (int nt = 0; nt < 4; ++nt) {
                const int j = j0 + wn * 32 + nt * 8 + 2 * (lane & 3);
                const int d = j >> 1;
                const float num = acc[mt][nt][half * 2 + 0];
                const float den = acc[mt][nt][half * 2 + 1];
                float w = num / den;
                if (!isfinite(w)) w = 0.f;
                const float o = sqrow[d] * w;
                bf16 h, l;
                split2(o, h, l);
                ah[d] = h;
                al[d] = l;
            }
        }
}

// ===========================================================================
// score_mma: D[n][m] = AF(n,d) @ J(m,d)^T (K=256); epilogue tanh-clip -> g_S
// grid (m 4, n 4, b)
// ===========================================================================
__global__ __launch_bounds__(256) void score_mma_kernel(
    const float* __restrict__ cost, const float* __restrict__ mask,
    const float* __restrict__ alpha2, const float* __restrict__ log_scale)
{
    extern __shared__ char smem[];
    const uint32_t sb = smem_u32(smem);
    const int b = blockIdx.z, n0 = blockIdx.y * 128, m0 = blockIdx.x * 128;
    const int tid = threadIdx.x, lane = tid & 31, wid = tid >> 5;
    const int wm = wid & 1, wn = wid >> 1;

    float acc[4][4][4] = {};
    const bf16* Ah = g_AFh + ((size_t)b * NP + n0) * DD;
    const bf16* Al = g_AFl + ((size_t)b * NP + n0) * DD;
    const bf16* Bh = g_Jh + ((size_t)b * MP + m0) * DD;
    const bf16* Bl = g_Jl + ((size_t)b * MP + m0) * DD;
    const bf16* Aps[3] = {Ah, Al, Ah};
    const bf16* Bps[3] = {Bh, Bh, Bl};
    mma_mainloop<3, 4>(sb, Aps, DD, Bps, DD, acc);

    const float c2 = alpha2[0] * log_scale[0];
#pragma unroll
    for (int mt = 0; mt < 4; ++mt)
#pragma unroll
        for (int half = 0; half < 2; ++half) {
            const int n = n0 + wm * 64 + mt * 16 + (lane >> 2) + half * 8;
            if (n >= NN) continue;
            const size_t rowoff = ((size_t)b * NN + n) * MM;
#pragma unroll
            for (int nt = 0; nt < 4; ++nt) {
                const int m = m0 + wn * 32 + nt * 8 + 2 * (lane & 3);
                if (m >= MM) continue;          // m even => m+1 < MM too
                const float v0 = acc[mt][nt][half * 2 + 0];
                const float v1 = acc[mt][nt][half * 2 + 1];
                const float2 cc = *(const float2*)(cost + rowoff + m);
                const float2 mk = *(const float2*)(mask + rowoff + m);
                float2 o;
                o.x = 10.f * tanhf(fmaf(v0, 0.0625f, -c2 * cc.x)) + mk.x;
                o.y = 10.f * tanhf(fmaf(v1, 0.0625f, -c2 * cc.y)) + mk.y;
                *(float2*)(g_S + rowoff + m) = o;
            }
        }
}

// ===========================================================================
// projkv_mma: D[m][j] = jobs(m,d) @ WKV(j,d)^T (K=256, j interleaved k/v).
// Epilogue writes transposed K2[j][m] = (j even: exp(k)*v ; j odd: exp(k)),
// zeros for padded m >= 500.  grid (j 4, m 4, b)
// ===========================================================================
__global__ __launch_bounds__(256) void projkv_mma_kernel()
{
    extern __shared__ char smem[];
    const uint32_t sb = smem_u32(smem);
    const int b = blockIdx.z, m0 = blockIdx.y * 128, j0 = blockIdx.x * 128;
    const int tid = threadIdx.x, lane = tid & 31, wid = tid >> 5;
    const int wm = wid & 1, wn = wid >> 1;

    float acc[4][4][4] = {};
    const bf16* Ah = g_Jh + ((size_t)b * MP + m0) * DD;
    const bf16* Al = g_Jl + ((size_t)b * MP + m0) * DD;
    const bf16* Bh = g_WKVh + (size_t)j0 * DD;
    const bf16* Bl = g_WKVl + (size_t)j0 * DD;
    const bf16* Aps[3] = {Ah, Al, Ah};
    const bf16* Bps[3] = {Bh, Bh, Bl};
    mma_mainloop<3, 4>(sb, Aps, DD, Bps, DD, acc);

#pragma unroll
    for (int mt = 0; mt < 4; ++mt)
#pragma unroll
        for (int half = 0; half < 2; ++half) {
            const int m = m0 + wm * 64 + mt * 16 + (lane >> 2) + half * 8;
            const bool valid = (m < MM);
#pragma unroll
            for (int nt = 0; nt < 4; ++nt) {
                const int j = j0 + wn * 32 + nt * 8 + 2 * (lane & 3);
                float ek = 0.f, ekv = 0.f;
                if (valid) {
                    ek = expf(acc[mt][nt][half * 2 + 0]);
                    ekv = ek * acc[mt][nt][half * 2 + 1];
                }
                bf16 h, l;
                split2(ekv, h, l);
                g_K2h[((size_t)b * NP + j) * MP + m] = h;
                g_K2l[((size_t)b * NP + j) * MP + m] = l;
                split2(ek, h, l);
                g_K2h[((size_t)b * NP + j + 1) * MP + m] = h;
                g_K2l[((size_t)b * NP + j + 1) * MP + m] = l;
            }
        }
}

// ===========================================================================
// projq_mma: q = q0@Wq0^T + q1@Wq1^T (6 split phases), sigmoid -> g_SQ fp32
// grid (e 2, n 4, b)
// ===========================================================================
__global__ __launch_bounds__(256) void projq_mma_kernel()
{
    extern __shared__ char smem[];
    const uint32_t sb = smem_u32(smem);
    const int b = blockIdx.z, n0 = blockIdx.y * 128, e0 = blockIdx.x * 128;
    const int tid = threadIdx.x, lane = tid & 31, wid = tid >> 5;
    const int wm = wid & 1, wn = wid >> 1;

    float acc[4][4][4] = {};
    const bf16* A0h = g_Q0h + ((size_t)b * NP + n0) * DD;
    const bf16* A0l = g_Q0l + ((size_t)b * NP + n0) * DD;
    const bf16* A1h = g_Q1h + ((size_t)b * NP + n0) * DD;
    const bf16* A1l = g_Q1l + ((size_t)b * NP + n0) * DD;
    const bf16* B0h = g_W0h + (size_t)e0 * DD;
    const bf16* B0l = g_W0l + (size_t)e0 * DD;
    const bf16* B1h = g_W1h + (size_t)e0 * DD;
    const bf16* B1l = g_W1l + (size_t)e0 * DD;
    const bf16* Aps[6] = {A0h, A0l, A0h, A1h, A1l, A1h};
    const bf16* Bps[6] = {B0h, B0h, B0l, B1h, B1h, B1l};
    mma_mainloop<6, 4>(sb, Aps, DD, Bps, DD, acc);

#pragma unroll
    for (int mt = 0; mt < 4; ++mt)
#pragma unroll
        for (int half = 0; half < 2; ++half) {
            const int n = n0 + wm * 64 + mt * 16 + (lane >> 2) + half * 8;
            if (n >= NN) continue;
            float* out = g_SQ + ((size_t)b * NN + n) * DD;
#pragma unroll
            for (int nt = 0; nt < 4; ++nt) {
                const int e = e0 + wn * 32 + nt * 8 + 2 * (lane & 3);
                float2 o;
                o.x = 1.f / (1.f + expf(-acc[mt][nt][half * 2 + 0]));
                o.y = 1.f / (1.f + expf(-acc[mt][nt][half * 2 + 1]));
                *(float2*)(out + e) = o;
            }
        }
}

// ===========================================================================
// eb_split: EB = exp(-a1*ls*cost + mask), padded [512][512], bf16 hi/lo
// ===========================================================================
__global__ __launch_bounds__(256) void eb_split_kernel(
    const float* __restrict__ cost, const float* __restrict__ mask,
    const float* __restrict__ alpha1, const float* __restrict__ log_scale)
{
    const float s1 = -alpha1[0] * log_scale[0];
    const int i = blockIdx.x * 256 + threadIdx.x;  // [0, 32*512*128)
    const int m4 = (i & 127) << 2;
    const int n = (i >> 7) & 511;
    const int b = i >> 16;
    bf16 h[4], l[4];
    const size_t crow = ((size_t)b * NN + n) * MM;
#pragma unroll
    for (int t = 0; t < 4; ++t) {
        int m = m4 + t;
        float x = 0.f;
        if (n < NN && m < MM)
            x = expf(fmaf(s1, cost[crow + m], mask[crow + m]));
        split2(x, h[t], l[t]);
    }
    const size_t o = ((size_t)b * NP + n) * MP + m4;
    st_b162(g_EBh + o, h[0], h[1]); st_b162(g_EBh + o + 2, h[2], h[3]);
    st_b162(g_EBl + o, l[0], l[1]); st_b162(g_EBl + o + 2, l[2], l[3]);
}

// ===========================================================================
// split_pad<SEL>: [BB][512][256] bf16 hi/lo split with zero row padding.
// SEL: 0 = jobs -> g_J*, 1 = q0 -> g_Q0*, 2 = q1 -> g_Q1*.
// Destination globals are resolved in DEVICE code (host-side &__device__ is
// invalid — that bug was R7's 0.51 rel_err).
// ===========================================================================
template <int SEL>
__global__ __launch_bounds__(256) void split_pad_kernel(
    const float* __restrict__ src)
{
    bf16* dh = (SEL == 0) ? g_Jh : (SEL == 1) ? g_Q0h : g_Q1h;
    bf16* dl = (SEL == 0) ? g_Jl : (SEL == 1) ? g_Q0l : g_Q1l;
    const int validRows = (SEL == 0) ? MM : NN;
    const int i = blockIdx.x * 256 + threadIdx.x;  // [0, 32*512*64)
    const int c4 = (i & 63) << 2;
    const int m = (i >> 6) & 511;
    const int b = i >> 15;
    bf16 h[4], l[4];
#pragma unroll
    for (int t = 0; t < 4; ++t) {
        float x = (m < validRows)
                      ? src[((size_t)b * validRows + m) * DD + c4 + t]
                      : 0.f;
        split2(x, h[t], l[t]);
    }
    const size_t o = ((size_t)b * MP + m) * DD + c4;
    st_b162(dh + o, h[0], h[1]); st_b162(dh + o + 2, h[2], h[3]);
    st_b162(dl + o, l[0], l[1]); st_b162(dl + o + 2, l[2], l[3]);
}

// ===========================================================================
// w_split: split Wq0, Wq1 and interleave+split Wk/Wv (256x256 each)
// ===========================================================================
__global__ __launch_bounds__(256) void w_split_kernel(
    const float* __restrict__ Wq0, const float* __restrict__ Wq1,
    const float* __restrict__ Wk, const float* __restrict__ Wv)
{
    const int i = blockIdx.x * 256 + threadIdx.x;  // [0, 65536)
    const int e = i >> 8, k = i & 255;
    bf16 h, l;
    split2(Wq0[i], h, l); g_W0h[i] = h; g_W0l[i] = l;
    split2(Wq1[i], h, l); g_W1h[i] = h; g_W1l[i] = l;
    split2(Wk[i], h, l);
    g_WKVh[(size_t)(2 * e) * DD + k] = h; g_WKVl[(size_t)(2 * e) * DD + k] = l;
    split2(Wv[i], h, l);
    g_WKVh[(size_t)(2 * e + 1) * DD + k] = h;
    g_WKVl[(size_t)(2 * e + 1) * DD + k] = l;
}

// ===========================================================================
// softmax over last dim (M=500), one block per (b,n) row
// ===========================================================================
__global__ __launch_bounds__(256) void softmax_kernel(float* __restrict__ out)
{
    const int b = blockIdx.y, n = blockIdx.x;
    const float* row = g_S + ((size_t)b * NN + n) * MM;
    float* orow = out + ((size_t)b * NN + n) * MM;
    __shared__ float red[256];
    const int tid = threadIdx.x;
    float v0 = row[tid];
    float v1 = (tid + 256 < MM) ? row[tid + 256] : -INFINITY;
    red[tid] = fmaxf(v0, v1);
    __syncthreads();
    for (int s = 128; s > 0; s >>= 1) {
        if (tid < s) red[tid] = fmaxf(red[tid], red[tid + s]);
        __syncthreads();
    }
    const float mx = red[0];
    __syncthreads();
    float e0 = expf(v0 - mx);
    float e1 = (tid + 256 < MM) ? expf(v1 - mx) : 0.f;
    red[tid] = e0 + e1;
    __syncthreads();
    for (int s = 128; s > 0; s >>= 1) {
        if (tid < s) red[tid] += red[tid + s];
        __syncthreads();
    }
    const float inv = 1.f / red[0];
    orow[tid] = e0 * inv;
    if (tid + 256 < MM) orow[tid + 256] = e1 * inv;
}

// ---------------------------------------------------------------------------
extern "C" void kernel_launch(void* const* d_in, const int* in_sizes, int n_in,
                              void* d_out, int out_size)
{
    const float* q0        = (const float*)d_in[0];
    const float* jobs      = (const float*)d_in[1];
    const float* q1        = (const float*)d_in[2];
    const float* cost      = (const float*)d_in[3];
    const float* log_scale = (const float*)d_in[4];
    const float* mask      = (const float*)d_in[5];
    const float* Wq0       = (const float*)d_in[6];
    const float* Wq1       = (const float*)d_in[7];
    const float* Wk        = (const float*)d_in[8];
    const float* Wv        = (const float*)d_in[9];
    const float* a1        = (const float*)d_in[10];
    const float* a2        = (const float*)d_in[11];
    float* out = (float*)d_out;

    cudaFuncSetAttribute(aafm_mma_kernel,
                         cudaFuncAttributeMaxDynamicSharedMemorySize, SMEM_MMA);
    cudaFuncSetAttribute(score_mma_kernel,
                         cudaFuncAttributeMaxDynamicSharedMemorySize, SMEM_MMA);
    cudaFuncSetAttribute(projkv_mma_kernel,
                         cudaFuncAttributeMaxDynamicSharedMemorySize, SMEM_MMA);
    cudaFuncSetAttribute(projq_mma_kernel,
                         cudaFuncAttributeMaxDynamicSharedMemorySize, SMEM_MMA);

    dim3 blk(256);
    w_split_kernel<<<256, blk>>>(Wq0, Wq1, Wk, Wv);
    split_pad_kernel<0><<<4096, blk>>>(jobs);
    split_pad_kernel<1><<<4096, blk>>>(q0);
    split_pad_kernel<2><<<4096, blk>>>(q1);
    eb_split_kernel<<<8192, blk>>>(cost, mask, a1, log_scale);
    projkv_mma_kernel<<<dim3(4, 4, BB), blk, SMEM_MMA>>>();
    projq_mma_kernel<<<dim3(2, 4, BB), blk, SMEM_MMA>>>();
    aafm_mma_kernel<<<dim3(4, 4, BB), blk, SMEM_MMA>>>();
    score_mma_kernel<<<dim3(4, 4, BB), blk, SMEM_MMA>>>(cost, mask, a2, log_scale);
    softmax_kernel<<<dim3(NN, BB), blk>>>(out);
}